// round 7
// baseline (speedup 1.0000x reference)
#include <cuda_runtime.h>
#include <cstdint>

#define B_SIZE 4096
#define T_LEN  2048
#define THREADS 128
#define WARPS  (THREADS/32)
#define GRID   456

typedef unsigned long long ull;

__device__ int g_task_counter;
__device__ int g_order[B_SIZE];

// ---- packed f32x2 helpers ----
__device__ __forceinline__ ull pk2(float a, float b) {
    ull r; asm("mov.b64 %0, {%1, %2};" : "=l"(r) : "f"(a), "f"(b)); return r;
}
__device__ __forceinline__ void upk2(ull v, float& a, float& b) {
    asm("mov.b64 {%0, %1}, %2;" : "=f"(a), "=f"(b) : "l"(v));
}
__device__ __forceinline__ void ffma2(ull& d, ull a, ull b) {
    asm("fma.rn.f32x2 %0, %1, %2, %0;" : "+l"(d) : "l"(a), "l"(b));
}

// ---- fast transcendentals (MUFU) ----
__device__ __forceinline__ float ex2f(float x) {
    float r; asm("ex2.approx.f32 %0, %1;" : "=f"(r) : "f"(x)); return r;
}
__device__ __forceinline__ float rcpf(float x) {
    float r; asm("rcp.approx.f32 %0, %1;" : "=f"(r) : "f"(x)); return r;
}
#define L2E 1.4426950408889634f

// sigmoid(a0+a1), horizontal reduce fused into the exponent argument
__device__ __forceinline__ float sig2(float a0, float a1) {
    return rcpf(1.f + ex2f(fmaf(-L2E, a0, -L2E * a1)));
}
// tanh(a0+a1), reduce fused
__device__ __forceinline__ float tanh2(float a0, float a1) {
    return fmaf(-2.f, rcpf(1.f + ex2f(fmaf(2.f * L2E, a0, 2.f * L2E * a1))), 1.f);
}
__device__ __forceinline__ float sigf(float z)  { return rcpf(1.f + ex2f(-L2E * z)); }
__device__ __forceinline__ float tanhf_(float z){ return fmaf(-2.f, rcpf(1.f + ex2f(2.f * L2E * z)), 1.f); }

// ---- LPT scheduler: order tasks longest-first (16-step buckets) ----
__global__ void __launch_bounds__(128)
schedule_kernel(const int* __restrict__ lengths)
{
    __shared__ int s_hist[128];
    __shared__ int s_base[128];
    const int tid = threadIdx.x;
    s_hist[tid] = 0;
    __syncthreads();
    for (int i = tid; i < B_SIZE; i += 128) {
        int b = (T_LEN - lengths[i]) >> 4;   // bucket 0 = longest
        atomicAdd(&s_hist[b], 1);
    }
    __syncthreads();
    if (tid == 0) {
        int acc = 0;
        for (int b = 0; b < 128; b++) { s_base[b] = acc; acc += s_hist[b]; }
        g_task_counter = 0;
    }
    __syncthreads();
    s_hist[tid] = 0;
    __syncthreads();
    for (int i = tid; i < B_SIZE; i += 128) {
        int b = (T_LEN - lengths[i]) >> 4;
        int pos = s_base[b] + atomicAdd(&s_hist[b], 1);
        g_order[pos] = i;
    }
}

__global__ void __launch_bounds__(THREADS, 3)
bilstm_kernel(const float* __restrict__ x,
              const int*   __restrict__ lengths,
              const float* __restrict__ w_ih,
              const float* __restrict__ w_hh,
              const float* __restrict__ b_ih,
              const float* __restrict__ b_hh,
              const float* __restrict__ fc_w,
              const float* __restrict__ fc_b,
              const float* __restrict__ fc2_w,
              const float* __restrict__ fc2_b,
              float* __restrict__ out)
{
    __shared__ __align__(16) float  s_h[WARPS * 64];  // per warp: 2 halves x 32 h
    __shared__ float2 s_wb[128];                      // (w_ih[row], b_ih[row]+b_hh[row])

    const int tid  = threadIdx.x;
    const int lane = tid & 31;
    const int wid  = tid >> 5;
    const int half = lane >> 4;      // 0 = seq A, 1 = seq B
    const int hl   = lane & 15;      // unit base: owns units hl and hl+16

    for (int i = tid; i < 128; i += THREADS)
        s_wb[i] = make_float2(w_ih[i], b_ih[i] + b_hh[i]);
    __syncthreads();

    // ---- per-lane recurrent weights: 8 rows (2 units x 4 gates), 128 regs ----
    // row(m) = hl + 16*m :  m=0,2,4,6 -> unit hl gates i,f,g,o
    //                       m=1,3,5,7 -> unit hl+16 gates i,f,g,o
    ull W[8][16];
    #pragma unroll
    for (int m = 0; m < 8; m++) {
        const ull* p = (const ull*)(w_hh + (hl + 16 * m) * 32);
        #pragma unroll
        for (int j = 0; j < 16; j++) W[m][j] = p[j];
    }

    float* buf = s_h + wid * 64 + half * 32;   // this half's h vector

    for (;;) {
        int base = 0;
        if (lane == 0) base = atomicAdd(&g_task_counter, 2);
        base = __shfl_sync(0xffffffffu, base, 0);
        if (base >= B_SIZE) break;
        const int taskA = g_order[base];
        const int taskB = (base + 1 < B_SIZE) ? g_order[base + 1] : -1;
        const int mytask = half ? taskB : taskA;
        const int len = (mytask >= 0) ? lengths[mytask] : 0;
        const float* xb = x + (size_t)(mytask >= 0 ? mytask : 0) * T_LEN;
        const int tmax = __reduce_max_sync(0xffffffffu, len);
        const int myoff = tmax - len;

        float c0 = 0.f, c1 = 0.f, h0 = 0.f, h1 = 0.f;
        buf[hl] = 0.f; buf[hl + 16] = 0.f;
        __syncwarp();

        int t  = tmax - 1;
        int tj = t - myoff;                    // this half's time index
        float xv = __ldg(xb + (tj > 0 ? tj : 0));
        while (t >= 0) {
            const int tjn = tj - 1;
            float xn = __ldg(xb + (tjn > 0 ? tjn : 0));   // prefetch
            const bool valid = (tj >= 0);

            // init 8 gate accumulators: (bias + x*w_ih) in even slot
            ull acc[8];
            #pragma unroll
            for (int m = 0; m < 8; m++) {
                const float2 wb = s_wb[hl + 16 * m];
                acc[m] = pk2(fmaf(xv, wb.x, wb.y), 0.f);
            }

            // matvec: 128 FFMA2, 8 independent chains, h via broadcast LDS
            const ulonglong2* hp = (const ulonglong2*)buf;
            #pragma unroll
            for (int j = 0; j < 8; j++) {
                ulonglong2 q = hp[j];
                #pragma unroll
                for (int m = 0; m < 8; m++) {
                    ffma2(acc[m], W[m][2 * j],     q.x);
                    ffma2(acc[m], W[m][2 * j + 1], q.y);
                }
            }

            float a, b;
            // unit hl
            upk2(acc[0], a, b); const float iv0 = sig2(a, b);
            upk2(acc[2], a, b); const float fv0 = sig2(a, b);
            upk2(acc[4], a, b); const float gv0 = tanh2(a, b);
            upk2(acc[6], a, b); const float ov0 = sig2(a, b);
            const float cn0 = fmaf(fv0, c0, iv0 * gv0);
            const float hn0 = ov0 * tanhf_(cn0);
            c0 = valid ? cn0 : c0;
            h0 = valid ? hn0 : h0;
            // unit hl+16
            upk2(acc[1], a, b); const float iv1 = sig2(a, b);
            upk2(acc[3], a, b); const float fv1 = sig2(a, b);
            upk2(acc[5], a, b); const float gv1 = tanh2(a, b);
            upk2(acc[7], a, b); const float ov1 = sig2(a, b);
            const float cn1 = fmaf(fv1, c1, iv1 * gv1);
            const float hn1 = ov1 * tanhf_(cn1);
            c1 = valid ? cn1 : c1;
            h1 = valid ? hn1 : h1;

            buf[hl]      = h0;     // program order within converged warp:
            buf[hl + 16] = h1;     // all LDS above issued before these STS
            __syncwarp();
            xv = xn; tj = tjn; --t;
        }

        // ---- FC heads (cold path): all 32 lanes per sequence ----
        const float* bufA = s_h + wid * 64;
        {
            float u0 = __ldg(fc_b + lane);
            float u1 = __ldg(fc_b + 32 + lane);
            #pragma unroll
            for (int k = 0; k < 32; k++) {
                const float hk = bufA[k];
                u0 = fmaf(__ldg(fc_w + lane * 32 + k),        hk, u0);
                u1 = fmaf(__ldg(fc_w + (32 + lane) * 32 + k), hk, u1);
            }
            u0 = (u0 > 0.f) ? u0 : (ex2f(L2E * u0) - 1.f);
            u1 = (u1 > 0.f) ? u1 : (ex2f(L2E * u1) - 1.f);
            float part = u0 * __ldg(fc2_w + lane) + u1 * __ldg(fc2_w + 32 + lane);
            #pragma unroll
            for (int s = 16; s; s >>= 1) part += __shfl_xor_sync(0xffffffffu, part, s);
            if (lane == 0) out[taskA] = sigf(part + __ldg(fc2_b));
        }
        if (taskB >= 0) {
            const float* bufB = bufA + 32;
            float u0 = __ldg(fc_b + lane);
            float u1 = __ldg(fc_b + 32 + lane);
            #pragma unroll
            for (int k = 0; k < 32; k++) {
                const float hk = bufB[k];
                u0 = fmaf(__ldg(fc_w + lane * 32 + k),        hk, u0);
                u1 = fmaf(__ldg(fc_w + (32 + lane) * 32 + k), hk, u1);
            }
            u0 = (u0 > 0.f) ? u0 : (ex2f(L2E * u0) - 1.f);
            u1 = (u1 > 0.f) ? u1 : (ex2f(L2E * u1) - 1.f);
            float part = u0 * __ldg(fc2_w + lane) + u1 * __ldg(fc2_w + 32 + lane);
            #pragma unroll
            for (int s = 16; s; s >>= 1) part += __shfl_xor_sync(0xffffffffu, part, s);
            if (lane == 0) out[taskB] = sigf(part + __ldg(fc2_b));
        }
        __syncwarp();   // protect buf reuse across tasks
    }
}

extern "C" void kernel_launch(void* const* d_in, const int* in_sizes, int n_in,
                              void* d_out, int out_size)
{
    const float* x       = (const float*)d_in[0];
    const int*   lengths = (const int*)  d_in[1];
    const float* w_ih    = (const float*)d_in[2];
    const float* w_hh    = (const float*)d_in[3];
    const float* b_ih    = (const float*)d_in[4];
    const float* b_hh    = (const float*)d_in[5];
    const float* fc_w    = (const float*)d_in[6];
    const float* fc_b    = (const float*)d_in[7];
    const float* fc2_w   = (const float*)d_in[8];
    const float* fc2_b   = (const float*)d_in[9];
    float* out = (float*)d_out;

    schedule_kernel<<<1, 128>>>(lengths);
    bilstm_kernel<<<GRID, THREADS>>>(x, lengths, w_ih, w_hh, b_ih, b_hh,
                                     fc_w, fc_b, fc2_w, fc2_b, out);
}

// round 8
// speedup vs baseline: 10.2385x; 10.2385x over previous
#include <cuda_runtime.h>
#include <cstdint>

#define B_SIZE 4096
#define T_LEN  2048
#define THREADS 128
#define WARPS  (THREADS/32)
#define GRID   304

typedef unsigned long long ull;

__device__ int g_task_counter;
__device__ int g_order[B_SIZE];

// ---- packed f32x2 helpers ----
__device__ __forceinline__ ull pk2(float a, float b) {
    ull r; asm("mov.b64 %0, {%1, %2};" : "=l"(r) : "f"(a), "f"(b)); return r;
}
__device__ __forceinline__ void upk2(ull v, float& a, float& b) {
    asm("mov.b64 {%0, %1}, %2;" : "=f"(a), "=f"(b) : "l"(v));
}
__device__ __forceinline__ void ffma2(ull& d, ull a, ull b) {
    asm("fma.rn.f32x2 %0, %1, %2, %0;" : "+l"(d) : "l"(a), "l"(b));
}

// ---- fast transcendentals (MUFU) ----
__device__ __forceinline__ float ex2f(float x) {
    float r; asm("ex2.approx.f32 %0, %1;" : "=f"(r) : "f"(x)); return r;
}
__device__ __forceinline__ float rcpf(float x) {
    float r; asm("rcp.approx.f32 %0, %1;" : "=f"(r) : "f"(x)); return r;
}
#define L2E 1.4426950408889634f

// sigmoid(a0+a1), horizontal reduce fused into the exponent argument
__device__ __forceinline__ float sig2(float a0, float a1) {
    return rcpf(1.f + ex2f(fmaf(-L2E, a0, -L2E * a1)));
}
// tanh(a0+a1), reduce fused
__device__ __forceinline__ float tanh2(float a0, float a1) {
    return fmaf(-2.f, rcpf(1.f + ex2f(fmaf(2.f * L2E, a0, 2.f * L2E * a1))), 1.f);
}
__device__ __forceinline__ float sigf(float z)  { return rcpf(1.f + ex2f(-L2E * z)); }
__device__ __forceinline__ float tanhf_(float z){ return fmaf(-2.f, rcpf(1.f + ex2f(2.f * L2E * z)), 1.f); }

// ---- LPT scheduler: order tasks longest-first (16-step buckets) ----
__global__ void __launch_bounds__(128)
schedule_kernel(const int* __restrict__ lengths)
{
    __shared__ int s_hist[128];
    __shared__ int s_base[128];
    const int tid = threadIdx.x;
    s_hist[tid] = 0;
    __syncthreads();
    for (int i = tid; i < B_SIZE; i += 128) {
        int b = (T_LEN - lengths[i]) >> 4;   // bucket 0 = longest
        atomicAdd(&s_hist[b], 1);
    }
    __syncthreads();
    if (tid == 0) {
        int acc = 0;
        for (int b = 0; b < 128; b++) { s_base[b] = acc; acc += s_hist[b]; }
        g_task_counter = 0;
    }
    __syncthreads();
    s_hist[tid] = 0;
    __syncthreads();
    for (int i = tid; i < B_SIZE; i += 128) {
        int b = (T_LEN - lengths[i]) >> 4;
        int pos = s_base[b] + atomicAdd(&s_hist[b], 1);
        g_order[pos] = i;
    }
}

__global__ void __launch_bounds__(THREADS, 2)
bilstm_kernel(const float* __restrict__ x,
              const int*   __restrict__ lengths,
              const float* __restrict__ w_ih,
              const float* __restrict__ w_hh,
              const float* __restrict__ b_ih,
              const float* __restrict__ b_hh,
              const float* __restrict__ fc_w,
              const float* __restrict__ fc_b,
              const float* __restrict__ fc2_w,
              const float* __restrict__ fc2_b,
              float* __restrict__ out)
{
    __shared__ __align__(16) float s_h[WARPS * 64];  // per warp: seqA 32 + seqB 32

    const int tid  = threadIdx.x;
    const int lane = tid & 31;
    const int wid  = tid >> 5;

    // ---- per-lane recurrent weights in registers (128 regs, shared by A and B) ----
    const int l = lane;
    const float bci = b_ih[l]      + b_hh[l];
    const float bcf = b_ih[32 + l] + b_hh[32 + l];
    const float bcg = b_ih[64 + l] + b_hh[64 + l];
    const float bco = b_ih[96 + l] + b_hh[96 + l];
    const float wxi = w_ih[l], wxf = w_ih[32 + l], wxg = w_ih[64 + l], wxo = w_ih[96 + l];

    ull wI[16], wF[16], wG[16], wO[16];
    {
        const ull* pI = (const ull*)(w_hh + (0  + l) * 32);
        const ull* pF = (const ull*)(w_hh + (32 + l) * 32);
        const ull* pG = (const ull*)(w_hh + (64 + l) * 32);
        const ull* pO = (const ull*)(w_hh + (96 + l) * 32);
        #pragma unroll
        for (int j = 0; j < 16; j++) { wI[j] = pI[j]; wF[j] = pF[j]; wG[j] = pG[j]; wO[j] = pO[j]; }
    }

    float* bufA = s_h + wid * 64;
    float* bufB = bufA + 32;

    for (;;) {
        int base = 0;
        if (lane == 0) base = atomicAdd(&g_task_counter, 2);
        base = __shfl_sync(0xffffffffu, base, 0);
        if (base >= B_SIZE) break;
        const int taskA = g_order[base];
        const int taskB = (base + 1 < B_SIZE) ? g_order[base + 1] : -1;
        const int lenA = lengths[taskA];
        const int lenB = (taskB >= 0) ? lengths[taskB] : 0;
        const float* xbA = x + (size_t)taskA * T_LEN;
        const float* xbB = x + (size_t)(taskB >= 0 ? taskB : 0) * T_LEN;

        int tjA = lenA - 1;
        int tjB = lenB - 1;
        int t   = (tjA > tjB ? tjA : tjB);

        float cA = 0.f, cB = 0.f, hA = 0.f, hB = 0.f;
        bufA[lane] = 0.f;
        bufB[lane] = 0.f;
        __syncwarp();

        float xvA = __ldg(xbA + (tjA > 0 ? tjA : 0));
        float xvB = __ldg(xbB + (tjB > 0 ? tjB : 0));
        while (t >= 0) {
            const float xnA = __ldg(xbA + (tjA - 1 > 0 ? tjA - 1 : 0));  // prefetch
            const float xnB = __ldg(xbB + (tjB - 1 > 0 ? tjB - 1 : 0));
            const bool vA = (tjA >= 0);
            const bool vB = (tjB >= 0);

            // gate accumulators for both sequences: 8 independent FFMA2 chains
            ull aiA = pk2(fmaf(xvA, wxi, bci), 0.f);
            ull afA = pk2(fmaf(xvA, wxf, bcf), 0.f);
            ull agA = pk2(fmaf(xvA, wxg, bcg), 0.f);
            ull aoA = pk2(fmaf(xvA, wxo, bco), 0.f);
            ull aiB = pk2(fmaf(xvB, wxi, bci), 0.f);
            ull afB = pk2(fmaf(xvB, wxf, bcf), 0.f);
            ull agB = pk2(fmaf(xvB, wxg, bcg), 0.f);
            ull aoB = pk2(fmaf(xvB, wxo, bco), 0.f);

            const ulonglong2* hpA = (const ulonglong2*)bufA;
            const ulonglong2* hpB = (const ulonglong2*)bufB;
            #pragma unroll
            for (int j = 0; j < 8; j++) {
                const ulonglong2 qA = hpA[j];
                ffma2(aiA, wI[2*j],     qA.x); ffma2(afA, wF[2*j],     qA.x);
                ffma2(agA, wG[2*j],     qA.x); ffma2(aoA, wO[2*j],     qA.x);
                ffma2(aiA, wI[2*j + 1], qA.y); ffma2(afA, wF[2*j + 1], qA.y);
                ffma2(agA, wG[2*j + 1], qA.y); ffma2(aoA, wO[2*j + 1], qA.y);
            }
            #pragma unroll
            for (int j = 0; j < 8; j++) {
                const ulonglong2 qB = hpB[j];
                ffma2(aiB, wI[2*j],     qB.x); ffma2(afB, wF[2*j],     qB.x);
                ffma2(agB, wG[2*j],     qB.x); ffma2(aoB, wO[2*j],     qB.x);
                ffma2(aiB, wI[2*j + 1], qB.y); ffma2(afB, wF[2*j + 1], qB.y);
                ffma2(agB, wG[2*j + 1], qB.y); ffma2(aoB, wO[2*j + 1], qB.y);
            }

            float a, b;
            // seq A activations
            upk2(aiA, a, b); const float ivA = sig2(a, b);
            upk2(afA, a, b); const float fvA = sig2(a, b);
            upk2(agA, a, b); const float gvA = tanh2(a, b);
            upk2(aoA, a, b); const float ovA = sig2(a, b);
            const float cnA = fmaf(fvA, cA, ivA * gvA);
            const float hnA = ovA * tanhf_(cnA);
            cA = vA ? cnA : cA;
            hA = vA ? hnA : hA;
            // seq B activations (independent chain, interleaved by scheduler)
            upk2(aiB, a, b); const float ivB = sig2(a, b);
            upk2(afB, a, b); const float fvB = sig2(a, b);
            upk2(agB, a, b); const float gvB = tanh2(a, b);
            upk2(aoB, a, b); const float ovB = sig2(a, b);
            const float cnB = fmaf(fvB, cB, ivB * gvB);
            const float hnB = ovB * tanhf_(cnB);
            cB = vB ? cnB : cB;
            hB = vB ? hnB : hB;

            bufA[lane] = hA;   // same-warp program order: all LDS above issued
            bufB[lane] = hB;   // before these STS; syncwarp publishes for next iter
            __syncwarp();
            xvA = xnA; xvB = xnB;
            --tjA; --tjB; --t;
        }

        // ---- FC heads (cold path) ----
        {
            float u0 = __ldg(fc_b + lane);
            float u1 = __ldg(fc_b + 32 + lane);
            #pragma unroll
            for (int k = 0; k < 32; k++) {
                const float hk = bufA[k];
                u0 = fmaf(__ldg(fc_w + lane * 32 + k),        hk, u0);
                u1 = fmaf(__ldg(fc_w + (32 + lane) * 32 + k), hk, u1);
            }
            u0 = (u0 > 0.f) ? u0 : (ex2f(L2E * u0) - 1.f);
            u1 = (u1 > 0.f) ? u1 : (ex2f(L2E * u1) - 1.f);
            float part = u0 * __ldg(fc2_w + lane) + u1 * __ldg(fc2_w + 32 + lane);
            #pragma unroll
            for (int s = 16; s; s >>= 1) part += __shfl_xor_sync(0xffffffffu, part, s);
            if (lane == 0) out[taskA] = sigf(part + __ldg(fc2_b));
        }
        if (taskB >= 0) {
            float u0 = __ldg(fc_b + lane);
            float u1 = __ldg(fc_b + 32 + lane);
            #pragma unroll
            for (int k = 0; k < 32; k++) {
                const float hk = bufB[k];
                u0 = fmaf(__ldg(fc_w + lane * 32 + k),        hk, u0);
                u1 = fmaf(__ldg(fc_w + (32 + lane) * 32 + k), hk, u1);
            }
            u0 = (u0 > 0.f) ? u0 : (ex2f(L2E * u0) - 1.f);
            u1 = (u1 > 0.f) ? u1 : (ex2f(L2E * u1) - 1.f);
            float part = u0 * __ldg(fc2_w + lane) + u1 * __ldg(fc2_w + 32 + lane);
            #pragma unroll
            for (int s = 16; s; s >>= 1) part += __shfl_xor_sync(0xffffffffu, part, s);
            if (lane == 0) out[taskB] = sigf(part + __ldg(fc2_b));
        }
        __syncwarp();   // protect buf reuse across tasks
    }
}

extern "C" void kernel_launch(void* const* d_in, const int* in_sizes, int n_in,
                              void* d_out, int out_size)
{
    const float* x       = (const float*)d_in[0];
    const int*   lengths = (const int*)  d_in[1];
    const float* w_ih    = (const float*)d_in[2];
    const float* w_hh    = (const float*)d_in[3];
    const float* b_ih    = (const float*)d_in[4];
    const float* b_hh    = (const float*)d_in[5];
    const float* fc_w    = (const float*)d_in[6];
    const float* fc_b    = (const float*)d_in[7];
    const float* fc2_w   = (const float*)d_in[8];
    const float* fc2_b   = (const float*)d_in[9];
    float* out = (float*)d_out;

    schedule_kernel<<<1, 128>>>(lengths);
    bilstm_kernel<<<GRID, THREADS>>>(x, lengths, w_ih, w_hh, b_ih, b_hh,
                                     fc_w, fc_b, fc2_w, fc2_b, out);
}

// round 10
// speedup vs baseline: 14.5149x; 1.4177x over previous
#include <cuda_runtime.h>
#include <cstdint>

#define B_SIZE 4096
#define T_LEN  2048
#define H_DIM  32
#define THREADS 128
#define WARPS  (THREADS/32)
#define GRID   456

typedef unsigned long long ull;

__device__ int g_task_counter;
__device__ int g_order[B_SIZE];

// ---- packed f32x2 helpers ----
__device__ __forceinline__ ull pk2(float a, float b) {
    ull r; asm("mov.b64 %0, {%1, %2};" : "=l"(r) : "f"(a), "f"(b)); return r;
}
__device__ __forceinline__ void upk2(ull v, float& a, float& b) {
    asm("mov.b64 {%0, %1}, %2;" : "=f"(a), "=f"(b) : "l"(v));
}
__device__ __forceinline__ void ffma2(ull& d, ull a, ull b) {
    asm("fma.rn.f32x2 %0, %1, %2, %0;" : "+l"(d) : "l"(a), "l"(b));
}

// ---- fast transcendentals: single-MUFU tanh (sm_75+) ----
__device__ __forceinline__ float tanha(float x) {
    float r; asm("tanh.approx.f32 %0, %1;" : "=f"(r) : "f"(x)); return r;
}
__device__ __forceinline__ float ex2f(float x) {
    float r; asm("ex2.approx.f32 %0, %1;" : "=f"(r) : "f"(x)); return r;
}
#define L2E 1.4426950408889634f

// sigmoid(a0+a1) = 0.5*tanh((a0+a1)/2) + 0.5   (1 MUFU)
__device__ __forceinline__ float sig2(float a0, float a1) {
    return fmaf(0.5f, tanha(fmaf(0.5f, a0, 0.5f * a1)), 0.5f);
}
// tanh(a0+a1)   (1 MUFU)
__device__ __forceinline__ float tanh2(float a0, float a1) {
    return tanha(a0 + a1);
}
__device__ __forceinline__ float sigf(float z) {
    return fmaf(0.5f, tanha(0.5f * z), 0.5f);
}

// ---- LPT scheduler: order tasks longest-first (16-step buckets) ----
__global__ void __launch_bounds__(128)
schedule_kernel(const int* __restrict__ lengths)
{
    __shared__ int s_hist[128];
    __shared__ int s_base[128];
    const int tid = threadIdx.x;
    s_hist[tid] = 0;
    __syncthreads();
    for (int i = tid; i < B_SIZE; i += 128) {
        int b = (T_LEN - lengths[i]) >> 4;   // bucket 0 = longest
        atomicAdd(&s_hist[b], 1);
    }
    __syncthreads();
    if (tid == 0) {
        int acc = 0;
        for (int b = 0; b < 128; b++) { s_base[b] = acc; acc += s_hist[b]; }
        g_task_counter = 0;
    }
    __syncthreads();
    s_hist[tid] = 0;
    __syncthreads();
    for (int i = tid; i < B_SIZE; i += 128) {
        int b = (T_LEN - lengths[i]) >> 4;
        int pos = s_base[b] + atomicAdd(&s_hist[b], 1);
        g_order[pos] = i;
    }
}

__global__ void __launch_bounds__(THREADS, 3)
bilstm_kernel(const float* __restrict__ x,
              const int*   __restrict__ lengths,
              const float* __restrict__ w_ih,
              const float* __restrict__ w_hh,
              const float* __restrict__ b_ih,
              const float* __restrict__ b_hh,
              const float* __restrict__ fc_w,
              const float* __restrict__ fc_b,
              const float* __restrict__ fc2_w,
              const float* __restrict__ fc2_b,
              float* __restrict__ out)
{
    __shared__ __align__(16) float s_h[WARPS * 64];  // per-warp double-buffered h

    const int tid  = threadIdx.x;
    const int lane = tid & 31;
    const int wid  = tid >> 5;

    // ---- per-lane recurrent weights in registers (loaded once) ----
    const int l = lane;
    const float bci = b_ih[l]      + b_hh[l];
    const float bcf = b_ih[32 + l] + b_hh[32 + l];
    const float bcg = b_ih[64 + l] + b_hh[64 + l];
    const float bco = b_ih[96 + l] + b_hh[96 + l];
    const float wxi = w_ih[l], wxf = w_ih[32 + l], wxg = w_ih[64 + l], wxo = w_ih[96 + l];

    ull wI[16], wF[16], wG[16], wO[16];
    {
        const ull* pI = (const ull*)(w_hh + (0  + l) * H_DIM);
        const ull* pF = (const ull*)(w_hh + (32 + l) * H_DIM);
        const ull* pG = (const ull*)(w_hh + (64 + l) * H_DIM);
        const ull* pO = (const ull*)(w_hh + (96 + l) * H_DIM);
        #pragma unroll
        for (int j = 0; j < 16; j++) { wI[j] = pI[j]; wF[j] = pF[j]; wG[j] = pG[j]; wO[j] = pO[j]; }
    }

    float* hb = s_h + wid * 64;

    // ---- dynamic task loop: one warp = one sequence at a time (LPT order) ----
    for (;;) {
        unsigned tk = 0;
        if (lane == 0) tk = (unsigned)atomicAdd(&g_task_counter, 1);
        tk = __shfl_sync(0xffffffffu, tk, 0);
        if (tk >= B_SIZE) break;
        const int task = g_order[tk];

        const int len = lengths[task];
        const float* xb = x + (size_t)task * T_LEN;

        float c = 0.f;
        int pb = 0;
        hb[lane] = 0.f;
        __syncwarp();

        int t = len - 1;
        float xv = __ldg(xb + t);
        while (t >= 0) {
            const int tn = (t > 0) ? (t - 1) : 0;
            float xn = __ldg(xb + tn);   // prefetch next x off the critical chain

            // gate accumulators: (even-k partial, odd-k partial)
            ull ai = pk2(fmaf(xv, wxi, bci), 0.f);
            ull af = pk2(fmaf(xv, wxf, bcf), 0.f);
            ull ag = pk2(fmaf(xv, wxg, bcg), 0.f);
            ull ao = pk2(fmaf(xv, wxo, bco), 0.f);

            const ulonglong2* hp = (const ulonglong2*)(hb + pb);
            #pragma unroll
            for (int j = 0; j < 8; j++) {
                ulonglong2 q = hp[j];   // (h[4j],h[4j+1]) , (h[4j+2],h[4j+3])
                ffma2(ai, wI[2*j],     q.x); ffma2(af, wF[2*j],     q.x);
                ffma2(ag, wG[2*j],     q.x); ffma2(ao, wO[2*j],     q.x);
                ffma2(ai, wI[2*j + 1], q.y); ffma2(af, wF[2*j + 1], q.y);
                ffma2(ag, wG[2*j + 1], q.y); ffma2(ao, wO[2*j + 1], q.y);
            }
            float e0, e1;
            upk2(ai, e0, e1); const float iv = sig2(e0, e1);
            upk2(af, e0, e1); const float fv = sig2(e0, e1);
            upk2(ag, e0, e1); const float gv = tanh2(e0, e1);
            upk2(ao, e0, e1); const float ov = sig2(e0, e1);

            c = fmaf(fv, c, iv * gv);
            const float hn = ov * tanha(c);

            pb ^= 32;
            hb[pb + lane] = hn;
            __syncwarp();
            xv = xn;
            --t;
        }

        // ---- FC head (cold path: weights read straight from global) ----
        {
            float u0 = __ldg(fc_b + lane);
            float u1 = __ldg(fc_b + 32 + lane);
            #pragma unroll
            for (int k = 0; k < 32; k++) {
                const float hk = hb[pb + k];              // broadcast read
                u0 = fmaf(__ldg(fc_w + lane * 32 + k),        hk, u0);
                u1 = fmaf(__ldg(fc_w + (32 + lane) * 32 + k), hk, u1);
            }
            u0 = (u0 > 0.f) ? u0 : (ex2f(L2E * u0) - 1.f);
            u1 = (u1 > 0.f) ? u1 : (ex2f(L2E * u1) - 1.f);

            float part = u0 * __ldg(fc2_w + lane) + u1 * __ldg(fc2_w + 32 + lane);
            #pragma unroll
            for (int s = 16; s; s >>= 1) part += __shfl_xor_sync(0xffffffffu, part, s);
            if (lane == 0) out[task] = sigf(part + __ldg(fc2_b));
            __syncwarp();   // protect hb reuse across tasks
        }
    }
}

extern "C" void kernel_launch(void* const* d_in, const int* in_sizes, int n_in,
                              void* d_out, int out_size)
{
    const float* x       = (const float*)d_in[0];
    const int*   lengths = (const int*)  d_in[1];
    const float* w_ih    = (const float*)d_in[2];
    const float* w_hh    = (const float*)d_in[3];
    const float* b_ih    = (const float*)d_in[4];
    const float* b_hh    = (const float*)d_in[5];
    const float* fc_w    = (const float*)d_in[6];
    const float* fc_b    = (const float*)d_in[7];
    const float* fc2_w   = (const float*)d_in[8];
    const float* fc2_b   = (const float*)d_in[9];
    float* out = (float*)d_out;

    schedule_kernel<<<1, 128>>>(lengths);
    bilstm_kernel<<<GRID, THREADS>>>(x, lengths, w_ih, w_hh, b_ih, b_hh,
                                     fc_w, fc_b, fc2_w, fc2_b, out);
}